// round 3
// baseline (speedup 1.0000x reference)
#include <cuda_runtime.h>
#include <math.h>

#define NPTS 16384
#define HID  256
#define HALF 128
#define KNN  7            // k+1 smallest kept per row
#define NSPLIT 8
#define JCHUNK (NPTS / NSPLIT)   // 2048 points per chunk (32KB smem)
#define KTOT 384                  // stacked K = 256 + 128

// Scratch (device globals; no allocation allowed)
__device__ float g_best[NPTS * NSPLIT * KNN];   // biased d2 partial top-7
__device__ float g_mean[NPTS];                  // mean kNN distance per row
__device__ float g_A[NPTS * KTOT];              // stacked activations [h | u]

// ---------------------------------------------------------------------------
// Pass A: brute-force kNN, j-range split NSPLIT ways.
// Per pair: d'' = sq_j - 2*(x_i*x_j + y_i*y_j)  (true d2 = d'' + sq_i)
// ---------------------------------------------------------------------------
__global__ void __launch_bounds__(256) knn_pass(const float2* __restrict__ coords) {
    __shared__ float4 pts[JCHUNK];   // (x, y, x^2+y^2, pad)

    int split = blockIdx.x & (NSPLIT - 1);
    int rb    = blockIdx.x >> 3;
    int tid   = threadIdx.x;
    int jbase = split * JCHUNK;

    for (int j = tid; j < JCHUNK; j += 256) {
        float2 c = coords[jbase + j];
        pts[j] = make_float4(c.x, c.y, fmaf(c.x, c.x, c.y * c.y), 0.f);
    }
    __syncthreads();

    int row = rb * 256 + tid;
    float2 q = coords[row];
    float a = -2.f * q.x;
    float b = -2.f * q.y;

    float best[KNN];
#pragma unroll
    for (int t = 0; t < KNN; ++t) best[t] = 3.4e38f;

#pragma unroll 8
    for (int j = 0; j < JCHUNK; ++j) {
        float4 p = pts[j];
        float d = fmaf(b, p.y, fmaf(a, p.x, p.z));
        if (d < best[KNN - 1]) {
            best[KNN - 1] = d;
#pragma unroll
            for (int t = KNN - 1; t > 0; --t) {
                float lo = fminf(best[t - 1], best[t]);
                float hi = fmaxf(best[t - 1], best[t]);
                best[t - 1] = lo;
                best[t]     = hi;
            }
        }
    }

    float* dst = &g_best[(row * NSPLIT + split) * KNN];
#pragma unroll
    for (int t = 0; t < KNN; ++t) dst[t] = best[t];
}

// ---------------------------------------------------------------------------
// Pass B: merge NSPLIT partial top-7 lists -> top-7 -> mean of sqrt of
// entries 1..6 (entry 0 is self).
// ---------------------------------------------------------------------------
__global__ void __launch_bounds__(256) merge_pass(const float2* __restrict__ coords) {
    int row = blockIdx.x * 256 + threadIdx.x;

    float best[KNN];
#pragma unroll
    for (int t = 0; t < KNN; ++t) best[t] = 3.4e38f;

    const float* src = &g_best[row * NSPLIT * KNN];
#pragma unroll 4
    for (int i = 0; i < NSPLIT * KNN; ++i) {
        float d = src[i];
        if (d < best[KNN - 1]) {
            best[KNN - 1] = d;
#pragma unroll
            for (int t = KNN - 1; t > 0; --t) {
                float lo = fminf(best[t - 1], best[t]);
                float hi = fmaxf(best[t - 1], best[t]);
                best[t - 1] = lo;
                best[t]     = hi;
            }
        }
    }

    float2 q  = coords[row];
    float sq  = fmaf(q.x, q.x, q.y * q.y);
    float sum = 0.f;
#pragma unroll
    for (int t = 1; t < KNN; ++t)
        sum += sqrtf(fmaxf(best[t] + sq, 1e-12f));
    g_mean[row] = sum * (1.f / (float)(KNN - 1));
}

// ---------------------------------------------------------------------------
// Pass C: build stacked activations A[row] = [ silu(x@W1+b1) | silu(m@Wd1+bd1) ]
// ---------------------------------------------------------------------------
__global__ void __launch_bounds__(KTOT) build_A(const float2* __restrict__ coords,
                                                const float* __restrict__ W1,
                                                const float* __restrict__ b1,
                                                const float* __restrict__ Wd1,
                                                const float* __restrict__ bd1) {
    int row = blockIdx.x;
    int k   = threadIdx.x;
    float z;
    if (k < HID) {
        float2 q = coords[row];
        z = fmaf(q.x, W1[k], fmaf(q.y, W1[HID + k], b1[k]));
    } else {
        int   kd = k - HID;
        float m  = g_mean[row];
        z = fmaf(m, Wd1[kd], bd1[kd]);
    }
    float sil = z / (1.f + __expf(-z));
    g_A[row * KTOT + k] = sil;
}

// ---------------------------------------------------------------------------
// Pass D: out = A @ [W2; Wd2] + (b2 + bd2)
// M=16384, N=256, K=384.  BM=128, BN=128, BK=32, 256 threads, 8x8 per thread.
// ---------------------------------------------------------------------------
__global__ void __launch_bounds__(256) gemm_pass(const float* __restrict__ W2,
                                                 const float* __restrict__ b2,
                                                 const float* __restrict__ Wd2,
                                                 const float* __restrict__ bd2,
                                                 float* __restrict__ out) {
    __shared__ float As[128][32];
    __shared__ float Bs[32][128];

    int bn = blockIdx.x;   // 0..1
    int bm = blockIdx.y;   // 0..127
    int tid = threadIdx.x;

    int tr = tid >> 4;          // 0..15
    int tc = tid & 15;          // 0..15
    int m0 = tr * 8;
    int n0 = tc * 8;

    int rowBase = bm * 128;
    int nBase   = bn * 128;

    // A-load mapping: 4 x float4 per thread
    int am = tid >> 3;          // 0..31
    int ak = (tid & 7) * 4;     // 0..28
    // B-load mapping: 4 x float4 per thread
    int bk  = tid >> 5;         // 0..7
    int bn4 = (tid & 31) * 4;   // 0..124

    float acc[8][8];
#pragma unroll
    for (int i = 0; i < 8; ++i)
#pragma unroll
        for (int j = 0; j < 8; ++j) acc[i][j] = 0.f;

    for (int kt = 0; kt < KTOT; kt += 32) {
#pragma unroll
        for (int i = 0; i < 4; ++i) {
            int m = am + i * 32;
            float4 v = *(const float4*)&g_A[(rowBase + m) * KTOT + kt + ak];
            *(float4*)&As[m][ak] = v;
        }
#pragma unroll
        for (int i = 0; i < 4; ++i) {
            int kk    = bk + i * 8;
            int kglob = kt + kk;
            const float* src = (kglob < HID)
                                   ? &W2[kglob * HID + nBase + bn4]
                                   : &Wd2[(kglob - HID) * HID + nBase + bn4];
            float4 v = *(const float4*)src;
            *(float4*)&Bs[kk][bn4] = v;
        }
        __syncthreads();

#pragma unroll
        for (int kk = 0; kk < 32; ++kk) {
            float aReg[8], bReg[8];
#pragma unroll
            for (int i = 0; i < 8; ++i) aReg[i] = As[m0 + i][kk];
            *(float4*)&bReg[0] = *(const float4*)&Bs[kk][n0];
            *(float4*)&bReg[4] = *(const float4*)&Bs[kk][n0 + 4];
#pragma unroll
            for (int i = 0; i < 8; ++i)
#pragma unroll
                for (int j = 0; j < 8; ++j)
                    acc[i][j] = fmaf(aReg[i], bReg[j], acc[i][j]);
        }
        __syncthreads();
    }

#pragma unroll
    for (int i = 0; i < 8; ++i) {
        int row = rowBase + m0 + i;
#pragma unroll
        for (int j4 = 0; j4 < 2; ++j4) {
            int n = nBase + n0 + j4 * 4;
            float4 o;
            o.x = acc[i][j4 * 4 + 0] + b2[n + 0] + bd2[n + 0];
            o.y = acc[i][j4 * 4 + 1] + b2[n + 1] + bd2[n + 1];
            o.z = acc[i][j4 * 4 + 2] + b2[n + 2] + bd2[n + 2];
            o.w = acc[i][j4 * 4 + 3] + b2[n + 3] + bd2[n + 3];
            *(float4*)&out[row * HID + n] = o;
        }
    }
}

// ---------------------------------------------------------------------------
extern "C" void kernel_launch(void* const* d_in, const int* in_sizes, int n_in,
                              void* d_out, int out_size) {
    (void)in_sizes; (void)n_in; (void)out_size;
    const float2* coords = (const float2*)d_in[0];
    const float*  W1  = (const float*)d_in[1];
    const float*  b1  = (const float*)d_in[2];
    const float*  W2  = (const float*)d_in[3];
    const float*  b2  = (const float*)d_in[4];
    const float*  Wd1 = (const float*)d_in[5];
    const float*  bd1 = (const float*)d_in[6];
    const float*  Wd2 = (const float*)d_in[7];
    const float*  bd2 = (const float*)d_in[8];
    float* out = (float*)d_out;

    knn_pass<<<(NPTS / 256) * NSPLIT, 256>>>(coords);
    merge_pass<<<NPTS / 256, 256>>>(coords);
    build_A<<<NPTS, KTOT>>>(coords, W1, b1, Wd1, bd1);
    gemm_pass<<<dim3(2, 128), 256>>>(W2, b2, Wd2, bd2, out);
}